// round 9
// baseline (speedup 1.0000x reference)
#include <cuda_runtime.h>

#define NATOMS   1500
#define NODE_DIM 128
#define HIDDEN   64
#define MUL1E    64
#define HID1E    32
#define NUM_BASIS 20
#define T        16      // edge tile side
#define NT       94      // ceil(1500/16)
#define ROWF     13500   // floats per output row: 1500*9
#define BSTRIDE  148     // padded row stride for transposed buffer (floats)

// Per-node packed data: a[3], b[3], coord[3], pad[3]  (48B = 3 x float4)
__device__ __align__(16) float g_node[NATOMS * 12];

__device__ __forceinline__ float silu_f(float d) {
    return d / (1.f + __expf(-d));
}

// One warp per node. 8 warps/block; weights L1-resident across warps.
__global__ __launch_bounds__(256)
void node_kernel(
    const float* __restrict__ xs,   const float* __restrict__ xsph,
    const float* __restrict__ coord,
    const float* __restrict__ Wsi1, const float* __restrict__ Wsi2,
    const float* __restrict__ Wsj1, const float* __restrict__ Wsj2,
    const float* __restrict__ Wpi1, const float* __restrict__ Wpi2,
    const float* __restrict__ Wpj1, const float* __restrict__ Wpj2)
{
    int w    = threadIdx.x >> 5;
    int lane = threadIdx.x & 31;
    int n    = blockIdx.x * 8 + w;

    __shared__ float sx[8][NODE_DIM];
    __shared__ float sv[8][MUL1E * 3];

    if (n >= NATOMS) return;           // warp-uniform

    // x: 128 floats = 32 float4, one per lane
    ((float4*)sx[w])[lane] = ((const float4*)(xs + n * NODE_DIM))[lane];
    // 1e block: 192 floats = 48 float4
    {
        const float4* vsrc = (const float4*)(xsph + n * 480 + 128);
        ((float4*)sv[w])[lane] = vsrc[lane];
        if (lane < 16) ((float4*)sv[w])[32 + lane] = vsrc[32 + lane];
    }
    __syncwarp();

    // ---- scalar MLPs: lanes 0-15 role i, lanes 16-31 role j; 4 h per lane
    const float* W1 = (lane < 16) ? Wsi1 : Wsj1;
    const float* W2 = (lane < 16) ? Wsi2 : Wsj2;
    int hb = 4 * (lane & 15);
    float a0 = 0.f, a1 = 0.f, a2 = 0.f, a3 = 0.f;
    #pragma unroll 8
    for (int f = 0; f < NODE_DIM; f++) {
        float xf = sx[w][f];
        float4 wv = *(const float4*)(W1 + f * HIDDEN + hb);
        a0 += xf * wv.x; a1 += xf * wv.y; a2 += xf * wv.z; a3 += xf * wv.w;
    }
    float4 w2v = *(const float4*)(W2 + hb);
    float v = silu_f(a0) * w2v.x + silu_f(a1) * w2v.y
            + silu_f(a2) * w2v.z + silu_f(a3) * w2v.w;
    #pragma unroll
    for (int off = 1; off < 16; off <<= 1) v += __shfl_xor_sync(0xffffffffu, v, off);
    // v = role sum on every lane of its 16-group

    // ---- spherical MLPs: lanes 0-15 role i, 16-31 role j; 2 h per lane
    const float* P1 = (lane < 16) ? Wpi1 : Wpj1;
    const float* P2 = (lane < 16) ? Wpi2 : Wpj2;
    int ph = 2 * (lane & 15);
    float h00 = 0.f, h01 = 0.f, h02 = 0.f;
    float h10 = 0.f, h11 = 0.f, h12 = 0.f;
    #pragma unroll 8
    for (int m = 0; m < MUL1E; m++) {
        float v0 = sv[w][3 * m + 0], v1 = sv[w][3 * m + 1], v2 = sv[w][3 * m + 2];
        float2 pw = *(const float2*)(P1 + m * HID1E + ph);
        h00 += v0 * pw.x; h01 += v1 * pw.x; h02 += v2 * pw.x;
        h10 += v0 * pw.y; h11 += v1 * pw.y; h12 += v2 * pw.y;
    }
    h00 *= 0.125f; h01 *= 0.125f; h02 *= 0.125f;   // / sqrt(64)
    h10 *= 0.125f; h11 *= 0.125f; h12 *= 0.125f;
    float2 p2v = *(const float2*)(P2 + ph);
    float n0 = sqrtf(h00 * h00 + h01 * h01 + h02 * h02);
    float n1 = sqrtf(h10 * h10 + h11 * h11 + h12 * h12);
    float wa = p2v.x / (1.f + __expf(-n0));        // W2 * sigmoid(|h|)
    float wb = p2v.y / (1.f + __expf(-n1));
    float o0 = h00 * wa + h10 * wb;
    float o1 = h01 * wa + h11 * wb;
    float o2 = h02 * wa + h12 * wb;
    #pragma unroll
    for (int off = 1; off < 16; off <<= 1) {
        o0 += __shfl_xor_sync(0xffffffffu, o0, off);
        o1 += __shfl_xor_sync(0xffffffffu, o1, off);
        o2 += __shfl_xor_sync(0xffffffffu, o2, off);
    }

    // gather role-j results from lane 16
    float vj  = __shfl_sync(0xffffffffu, v,  16);
    float oj0 = __shfl_sync(0xffffffffu, o0, 16);
    float oj1 = __shfl_sync(0xffffffffu, o1, 16);
    float oj2 = __shfl_sync(0xffffffffu, o2, 16);

    if (lane == 0) {
        const float inv32 = 0.17677669529663689f;  // 1/sqrt(32)
        float fa = (1.f + v)  * inv32;
        float fb = (1.f + vj) * inv32;
        float cx = coord[n * 3 + 0], cy = coord[n * 3 + 1], cz = coord[n * 3 + 2];
        float4* gp = (float4*)(g_node + n * 12);
        // e3nn (y,z,x) -> (x,y,z) permutation [2,0,1], fold in gate (1+s)
        gp[0] = make_float4(o2  * fa, o0  * fa, o1  * fa, oj2 * fb);
        gp[1] = make_float4(oj0 * fb, oj1 * fb, cx, cy);
        gp[2] = make_float4(cz, 0.f, 0.f, 0.f);
    }
}

// Symmetric 16x16 tiles over the upper triangle; dual-layout smem staging.
__global__ __launch_bounds__(256)
void edge_kernel(const float* __restrict__ Wrbf, float* __restrict__ out)
{
    int b = blockIdx.x;
    // triangular decode (once per block)
    int ti = (int)((2.f * NT + 1.f - sqrtf((2.f * NT + 1.f) * (2.f * NT + 1.f) - 8.f * (float)b)) * 0.5f);
    if (ti < 0) ti = 0; if (ti > NT - 1) ti = NT - 1;
    while (ti * NT - ti * (ti - 1) / 2 > b) ti--;
    while ((ti + 1) * NT - (ti + 1) * ti / 2 <= b) ti++;
    int tj = ti + (b - (ti * NT - ti * (ti - 1) / 2));

    int t  = threadIdx.x;
    int tx = t & 15;        // j within tile
    int ty = t >> 4;        // i within tile

    __shared__ __align__(16) float sbufA[T * T * 9];      // [ii][jj*9+c], row stride 144
    __shared__ __align__(16) float sbufB[T * BSTRIDE];    // [jj][ii*9+cT], row stride 148
    __shared__ __align__(16) float4 gi4[T][3];
    __shared__ __align__(16) float4 gj4[T][3];
    __shared__ float sWp[33];   // zero-padded: sWp[k+4] = W[k], k in [0,20)

    if (t < 33) {
        int k = t - 4;
        sWp[t] = (k >= 0 && k < NUM_BASIS) ? Wrbf[k] : 0.f;
    }
    // vectorized cooperative tile loads: 48 float4 each, independent ranges
    if (t >= 64 && t < 112) {
        int u = t - 64;                     // 0..47
        int n = ti * T + u / 3;
        ((float4*)gi4)[u] = (n < NATOMS) ? ((const float4*)g_node)[n * 3 + u % 3]
                                         : make_float4(0.f, 0.f, 0.f, 0.f);
    }
    if (t >= 128 && t < 176) {
        int u = t - 128;
        int n = tj * T + u / 3;
        ((float4*)gj4)[u] = (n < NATOMS) ? ((const float4*)g_node)[n * 3 + u % 3]
                                         : make_float4(0.f, 0.f, 0.f, 0.f);
    }
    __syncthreads();

    int vi = NATOMS - ti * T; if (vi > T) vi = T;
    int vj = NATOMS - tj * T; if (vj > T) vj = T;
    bool offdiag = (ti != tj);

    if (ty < vi && tx < vj) {
        float4 i0 = gi4[ty][0], i1 = gi4[ty][1], i2 = gi4[ty][2];
        float4 j0 = gj4[tx][0], j1 = gj4[tx][1], j2 = gj4[tx][2];

        float dx = i1.z - j1.z, dy = i1.w - j1.w, dz = i2.x - j2.x;
        float d = sqrtf(dx * dx + dy * dy + dz * dz);

        float h = 0.f;
        if (d <= 6.3f) {      // beyond 6.3: fc < ~4e-6 of typical -> exact zero
            const float delta = 5.0f / 19.0f;
            const float coeff = -0.5f / (delta * delta);
            int k0 = __float2int_rn(d * (19.0f / 5.0f));
            int k0c = min(k0, 24);
            float u0 = d - (float)(k0c - 4) * delta;   // u for kk=0
            float fc = 0.f;
            #pragma unroll
            for (int kk = 0; kk < 9; kk++) {
                float u = u0 - (float)kk * delta;
                fc += sWp[k0c + kk] * __expf(coeff * u * u);
            }
            h = 0.5f * fc;
        }

        float ai0 = i0.x * h, ai1 = i0.y * h, ai2 = i0.z * h;
        float bi0 = i0.w * h, bi1 = i1.x * h, bi2 = i1.y * h;
        float aj0 = j0.x, aj1 = j0.y, aj2 = j0.z;
        float bj0 = j0.w, bj1 = j1.x, bj2 = j1.y;

        float m00 = ai0 * bj0 + bi0 * aj0;
        float m01 = ai0 * bj1 + bi0 * aj1;
        float m02 = ai0 * bj2 + bi0 * aj2;
        float m10 = ai1 * bj0 + bi1 * aj0;
        float m11 = ai1 * bj1 + bi1 * aj1;
        float m12 = ai1 * bj2 + bi1 * aj2;
        float m20 = ai2 * bj0 + bi2 * aj0;
        float m21 = ai2 * bj1 + bi2 * aj1;
        float m22 = ai2 * bj2 + bi2 * aj2;

        float* a = sbufA + ty * (T * 9) + tx * 9;
        a[0] = m00; a[1] = m01; a[2] = m02;
        a[3] = m10; a[4] = m11; a[5] = m12;
        a[6] = m20; a[7] = m21; a[8] = m22;

        if (offdiag) {
            float* bq = sbufB + tx * BSTRIDE + ty * 9;   // transposed block
            bq[0] = m00; bq[1] = m10; bq[2] = m20;
            bq[3] = m01; bq[4] = m11; bq[5] = m21;
            bq[6] = m02; bq[7] = m12; bq[8] = m22;
        }
    }
    __syncthreads();

    // Direct tile: row ii -> vj*9 floats at out[(ti*T+ii)*ROWF + tj*T*9]
    if (ty < vi) {
        int w4 = (vj * 9) >> 2;    // vj in {16,12} -> divisible by 4
        const float4* src = (const float4*)(sbufA + ty * (T * 9));
        float4* dst = (float4*)(out + (size_t)(ti * T + ty) * ROWF + (size_t)tj * T * 9);
        #pragma unroll
        for (int c = tx; c < 36; c += 16)
            if (c < w4) dst[c] = src[c];
    }

    // Transposed tile: row jj -> vi*9 floats at out[(tj*T+jj)*ROWF + ti*T*9]
    if (offdiag && ty < vj) {
        int w4 = (vi * 9) >> 2;
        const float4* src = (const float4*)(sbufB + ty * BSTRIDE);
        float4* dst = (float4*)(out + (size_t)(tj * T + ty) * ROWF + (size_t)ti * T * 9);
        #pragma unroll
        for (int c = tx; c < 36; c += 16)
            if (c < w4) dst[c] = src[c];
    }
}

extern "C" void kernel_launch(void* const* d_in, const int* in_sizes, int n_in,
                              void* d_out, int out_size)
{
    const float* xs    = (const float*)d_in[0];
    const float* xsph  = (const float*)d_in[1];
    const float* coord = (const float*)d_in[2];
    // d_in[3] = fc_edge_index (int32, full graph i-major) — structure fixed, unused
    const float* Wsi1 = (const float*)d_in[4];
    const float* Wsi2 = (const float*)d_in[5];
    const float* Wsj1 = (const float*)d_in[6];
    const float* Wsj2 = (const float*)d_in[7];
    const float* Wpi1 = (const float*)d_in[8];
    const float* Wpi2 = (const float*)d_in[9];
    const float* Wpj1 = (const float*)d_in[10];
    const float* Wpj2 = (const float*)d_in[11];
    const float* Wrbf = (const float*)d_in[12];
    float* out = (float*)d_out;

    node_kernel<<<(NATOMS + 7) / 8, 256>>>(xs, xsph, coord,
                                           Wsi1, Wsi2, Wsj1, Wsj2,
                                           Wpi1, Wpi2, Wpj1, Wpj2);

    int nblocks = NT * (NT + 1) / 2;   // 4465 upper-triangle tiles
    edge_kernel<<<nblocks, 256>>>(Wrbf, out);
}

// round 10
// speedup vs baseline: 1.3070x; 1.3070x over previous
#include <cuda_runtime.h>

#define NATOMS   1500
#define NODE_DIM 128
#define HIDDEN   64
#define MUL1E    64
#define HID1E    32
#define NUM_BASIS 20
#define T        16      // edge tile side
#define NT       94      // ceil(1500/16)
#define ROWF     13500   // floats per output row: 1500*9
#define BSTRIDE  148     // padded row stride for transposed buffer (floats)
#define NBLK     148     // node kernel blocks (1/SM)
#define KP       4       // nodes per pass
#define NPASS    3       // ceil(ceil(1500/148)/4)

// Per-node packed data: a[3], b[3], coord[3], pad[3]  (48B = 3 x float4)
__device__ __align__(16) float g_node[NATOMS * 12];

__device__ __forceinline__ float silu_f(float d) {
    return d / (1.f + __expf(-d));
}

// dynamic smem layout (float offsets)
#define OFF_WS1  0        // [128][128]: col<64 -> Wsi1, col>=64 -> Wsj1
#define OFF_WP1  16384    // [64][64]:   col<32 -> Wpi1, col>=32 -> Wpj1
#define OFF_W2S  20480    // [128]: 0..63 Wsi2, 64..127 Wsj2
#define OFF_WP2  20608    // [64]:  0..31 Wpi2, 32..63 Wpj2
#define OFF_SX   20672    // [KP][128]
#define OFF_SV   21184    // [KP][192]
#define OFF_RED  21952    // scalar partials [2 role][2 half][KP] = 16
#define OFF_SRED 21968    // sph sums [2 role][KP][3] = 24
#define SMEM_FLOATS 22016
#define SMEM_BYTES  (SMEM_FLOATS * 4)

__global__ __launch_bounds__(256, 1)
void node_kernel(
    const float* __restrict__ xs,   const float* __restrict__ xsph,
    const float* __restrict__ coord,
    const float* __restrict__ Wsi1, const float* __restrict__ Wsi2,
    const float* __restrict__ Wsj1, const float* __restrict__ Wsj2,
    const float* __restrict__ Wpi1, const float* __restrict__ Wpi2,
    const float* __restrict__ Wpj1, const float* __restrict__ Wpj2)
{
    extern __shared__ __align__(16) float sm[];
    int t  = threadIdx.x;
    int bx = blockIdx.x;
    int lane = t & 31;

    // ---- load all weights into smem (once per block) ----
    for (int q = t; q < 8192; q += 256) {            // Wsi1 / Wsj1
        int f = q >> 6, h = q & 63;
        sm[OFF_WS1 + f * 128 + h]      = Wsi1[q];
        sm[OFF_WS1 + f * 128 + 64 + h] = Wsj1[q];
    }
    for (int q = t; q < 2048; q += 256) {            // Wpi1 / Wpj1
        int f = q >> 5, h = q & 31;
        sm[OFF_WP1 + f * 64 + h]      = Wpi1[q];
        sm[OFF_WP1 + f * 64 + 32 + h] = Wpj1[q];
    }
    if (t < 64) { sm[OFF_W2S + t] = Wsi2[t]; sm[OFF_W2S + 64 + t] = Wsj2[t]; }
    if (t < 32) { sm[OFF_WP2 + t] = Wpi2[t]; sm[OFF_WP2 + 32 + t] = Wpj2[t]; }

    for (int p = 0; p < NPASS; p++) {
        __syncthreads();   // weights ready / previous-pass writers done

        // ---- load KP nodes' features (zero-pad invalid) ----
        float4* sx4 = (float4*)(sm + OFF_SX);
        float4* sv4 = (float4*)(sm + OFF_SV);
        for (int q = t; q < KP * 32; q += 256) {     // x: 32 float4 per node
            int k = q >> 5, f4 = q & 31;
            int n = bx + NBLK * (p * KP + k);
            sx4[q] = (n < NATOMS) ? ((const float4*)(xs + (size_t)n * NODE_DIM))[f4]
                                  : make_float4(0.f, 0.f, 0.f, 0.f);
        }
        for (int q = t; q < KP * 48; q += 256) {     // 1e block: 48 float4 per node
            int k = q / 48, r = q % 48;
            int n = bx + NBLK * (p * KP + k);
            sv4[q] = (n < NATOMS) ? ((const float4*)(xsph + (size_t)n * 480 + 128))[r]
                                  : make_float4(0.f, 0.f, 0.f, 0.f);
        }
        __syncthreads();

        if (t < 128) {
            // ---- scalar MLPs: col = t (0..63 role i, 64..127 role j) ----
            int col = t;
            float a0 = 0.f, a1 = 0.f, a2 = 0.f, a3 = 0.f;
            const float* W = sm + OFF_WS1 + col;
            #pragma unroll 8
            for (int f4 = 0; f4 < 32; f4++) {
                float4 x0 = sx4[f4], x1 = sx4[32 + f4], x2 = sx4[64 + f4], x3 = sx4[96 + f4];
                float w;
                w = W[(f4 * 4 + 0) * 128]; a0 += x0.x * w; a1 += x1.x * w; a2 += x2.x * w; a3 += x3.x * w;
                w = W[(f4 * 4 + 1) * 128]; a0 += x0.y * w; a1 += x1.y * w; a2 += x2.y * w; a3 += x3.y * w;
                w = W[(f4 * 4 + 2) * 128]; a0 += x0.z * w; a1 += x1.z * w; a2 += x2.z * w; a3 += x3.z * w;
                w = W[(f4 * 4 + 3) * 128]; a0 += x0.w * w; a1 += x1.w * w; a2 += x2.w * w; a3 += x3.w * w;
            }
            float w2 = sm[OFF_W2S + col];
            float s0 = silu_f(a0) * w2, s1 = silu_f(a1) * w2;
            float s2 = silu_f(a2) * w2, s3 = silu_f(a3) * w2;
            #pragma unroll
            for (int off = 1; off < 32; off <<= 1) {
                s0 += __shfl_xor_sync(0xffffffffu, s0, off);
                s1 += __shfl_xor_sync(0xffffffffu, s1, off);
                s2 += __shfl_xor_sync(0xffffffffu, s2, off);
                s3 += __shfl_xor_sync(0xffffffffu, s3, off);
            }
            if (lane == 0) {
                int role = t >> 6, half = (t >> 5) & 1;
                float* rp = sm + OFF_RED + (role * 2 + half) * KP;
                rp[0] = s0; rp[1] = s1; rp[2] = s2; rp[3] = s3;
            }
        } else if (t < 192) {
            // ---- spherical MLPs: col = t-128 (0..31 role i, 32..63 role j) ----
            int col = t - 128;
            const float* sv = sm + OFF_SV;
            const float* P = sm + OFF_WP1 + col;
            float h00=0,h01=0,h02=0, h10=0,h11=0,h12=0, h20=0,h21=0,h22=0, h30=0,h31=0,h32=0;
            #pragma unroll 8
            for (int m = 0; m < MUL1E; m++) {
                float w = P[m * 64];
                h00 += sv[3*m+0] * w;     h01 += sv[3*m+1] * w;     h02 += sv[3*m+2] * w;
                h10 += sv[192+3*m+0] * w; h11 += sv[192+3*m+1] * w; h12 += sv[192+3*m+2] * w;
                h20 += sv[384+3*m+0] * w; h21 += sv[384+3*m+1] * w; h22 += sv[384+3*m+2] * w;
                h30 += sv[576+3*m+0] * w; h31 += sv[576+3*m+1] * w; h32 += sv[576+3*m+2] * w;
            }
            float w2c = sm[OFF_WP2 + col];
            float o[4][3];
            #pragma unroll
            for (int k = 0; k < 4; k++) {
                float u0, u1, u2;
                if (k == 0) { u0 = h00; u1 = h01; u2 = h02; }
                else if (k == 1) { u0 = h10; u1 = h11; u2 = h12; }
                else if (k == 2) { u0 = h20; u1 = h21; u2 = h22; }
                else { u0 = h30; u1 = h31; u2 = h32; }
                u0 *= 0.125f; u1 *= 0.125f; u2 *= 0.125f;       // / sqrt(64)
                float nr = sqrtf(u0*u0 + u1*u1 + u2*u2);
                float wg = w2c / (1.f + __expf(-nr));            // W2 * sigmoid(|h|)
                o[k][0] = u0 * wg; o[k][1] = u1 * wg; o[k][2] = u2 * wg;
            }
            #pragma unroll
            for (int off = 1; off < 32; off <<= 1)
                #pragma unroll
                for (int k = 0; k < 4; k++) {
                    o[k][0] += __shfl_xor_sync(0xffffffffu, o[k][0], off);
                    o[k][1] += __shfl_xor_sync(0xffffffffu, o[k][1], off);
                    o[k][2] += __shfl_xor_sync(0xffffffffu, o[k][2], off);
                }
            if (lane == 0) {
                int role = col >> 5;    // warp-aligned
                float* sp = sm + OFF_SRED + role * KP * 3;
                #pragma unroll
                for (int k = 0; k < 4; k++) {
                    sp[k*3+0] = o[k][0]; sp[k*3+1] = o[k][1]; sp[k*3+2] = o[k][2];
                }
            }
        }
        __syncthreads();

        if (t < KP) {
            int n = bx + NBLK * (p * KP + t);
            if (n < NATOMS) {
                const float inv32 = 0.17677669529663689f;   // 1/sqrt(32)
                float sI = sm[OFF_RED + 0 * KP + t] + sm[OFF_RED + 1 * KP + t];
                float sJ = sm[OFF_RED + 2 * KP + t] + sm[OFF_RED + 3 * KP + t];
                float fa = (1.f + sI) * inv32;
                float fb = (1.f + sJ) * inv32;
                const float* oI = sm + OFF_SRED + t * 3;
                const float* oJ = sm + OFF_SRED + KP * 3 + t * 3;
                float cx = coord[n*3+0], cy = coord[n*3+1], cz = coord[n*3+2];
                float4* gp = (float4*)(g_node + n * 12);
                // e3nn (y,z,x) -> (x,y,z) permutation [2,0,1], fold in gate (1+s)
                gp[0] = make_float4(oI[2]*fa, oI[0]*fa, oI[1]*fa, oJ[2]*fb);
                gp[1] = make_float4(oJ[0]*fb, oJ[1]*fb, cx, cy);
                gp[2] = make_float4(cz, 0.f, 0.f, 0.f);
            }
        }
    }
}

// Symmetric 16x16 tiles over the upper triangle; dual-layout smem staging.
__global__ __launch_bounds__(256)
void edge_kernel(const float* __restrict__ Wrbf, float* __restrict__ out)
{
    int b = blockIdx.x;
    // triangular decode (once per block)
    int ti = (int)((2.f * NT + 1.f - sqrtf((2.f * NT + 1.f) * (2.f * NT + 1.f) - 8.f * (float)b)) * 0.5f);
    if (ti < 0) ti = 0; if (ti > NT - 1) ti = NT - 1;
    while (ti * NT - ti * (ti - 1) / 2 > b) ti--;
    while ((ti + 1) * NT - (ti + 1) * ti / 2 <= b) ti++;
    int tj = ti + (b - (ti * NT - ti * (ti - 1) / 2));

    int t  = threadIdx.x;
    int tx = t & 15;        // j within tile
    int ty = t >> 4;        // i within tile

    __shared__ __align__(16) float sbufA[T * T * 9];      // [ii][jj*9+c]
    __shared__ __align__(16) float sbufB[T * BSTRIDE];    // [jj][ii*9+cT]
    __shared__ __align__(16) float4 gi4[T][3];
    __shared__ __align__(16) float4 gj4[T][3];
    __shared__ float sWp[33];   // zero-padded: sWp[k+4] = W[k]

    if (t < 33) {
        int k = t - 4;
        sWp[t] = (k >= 0 && k < NUM_BASIS) ? Wrbf[k] : 0.f;
    }
    if (t >= 64 && t < 112) {
        int u = t - 64;
        int n = ti * T + u / 3;
        ((float4*)gi4)[u] = (n < NATOMS) ? ((const float4*)g_node)[n * 3 + u % 3]
                                         : make_float4(0.f, 0.f, 0.f, 0.f);
    }
    if (t >= 128 && t < 176) {
        int u = t - 128;
        int n = tj * T + u / 3;
        ((float4*)gj4)[u] = (n < NATOMS) ? ((const float4*)g_node)[n * 3 + u % 3]
                                         : make_float4(0.f, 0.f, 0.f, 0.f);
    }
    __syncthreads();

    int vi = NATOMS - ti * T; if (vi > T) vi = T;
    int vj = NATOMS - tj * T; if (vj > T) vj = T;
    bool offdiag = (ti != tj);

    if (ty < vi && tx < vj) {
        float4 i0 = gi4[ty][0], i1 = gi4[ty][1], i2 = gi4[ty][2];
        float4 j0 = gj4[tx][0], j1 = gj4[tx][1], j2 = gj4[tx][2];

        float dx = i1.z - j1.z, dy = i1.w - j1.w, dz = i2.x - j2.x;
        float d = sqrtf(dx * dx + dy * dy + dz * dz);

        float h = 0.f;
        if (d <= 6.3f) {
            const float delta = 5.0f / 19.0f;
            const float coeff = -0.5f / (delta * delta);
            int k0 = __float2int_rn(d * (19.0f / 5.0f));
            int k0c = min(k0, 24);
            float u0 = d - (float)(k0c - 4) * delta;
            float fc = 0.f;
            #pragma unroll
            for (int kk = 0; kk < 9; kk++) {
                float u = u0 - (float)kk * delta;
                fc += sWp[k0c + kk] * __expf(coeff * u * u);
            }
            h = 0.5f * fc;
        }

        float ai0 = i0.x * h, ai1 = i0.y * h, ai2 = i0.z * h;
        float bi0 = i0.w * h, bi1 = i1.x * h, bi2 = i1.y * h;
        float aj0 = j0.x, aj1 = j0.y, aj2 = j0.z;
        float bj0 = j0.w, bj1 = j1.x, bj2 = j1.y;

        float m00 = ai0 * bj0 + bi0 * aj0;
        float m01 = ai0 * bj1 + bi0 * aj1;
        float m02 = ai0 * bj2 + bi0 * aj2;
        float m10 = ai1 * bj0 + bi1 * aj0;
        float m11 = ai1 * bj1 + bi1 * aj1;
        float m12 = ai1 * bj2 + bi1 * aj2;
        float m20 = ai2 * bj0 + bi2 * aj0;
        float m21 = ai2 * bj1 + bi2 * aj1;
        float m22 = ai2 * bj2 + bi2 * aj2;

        float* a = sbufA + ty * (T * 9) + tx * 9;
        a[0] = m00; a[1] = m01; a[2] = m02;
        a[3] = m10; a[4] = m11; a[5] = m12;
        a[6] = m20; a[7] = m21; a[8] = m22;

        if (offdiag) {
            float* bq = sbufB + tx * BSTRIDE + ty * 9;
            bq[0] = m00; bq[1] = m10; bq[2] = m20;
            bq[3] = m01; bq[4] = m11; bq[5] = m21;
            bq[6] = m02; bq[7] = m12; bq[8] = m22;
        }
    }
    __syncthreads();

    if (ty < vi) {
        int w4 = (vj * 9) >> 2;
        const float4* src = (const float4*)(sbufA + ty * (T * 9));
        float4* dst = (float4*)(out + (size_t)(ti * T + ty) * ROWF + (size_t)tj * T * 9);
        #pragma unroll
        for (int c = tx; c < 36; c += 16)
            if (c < w4) dst[c] = src[c];
    }

    if (offdiag && ty < vj) {
        int w4 = (vi * 9) >> 2;
        const float4* src = (const float4*)(sbufB + ty * BSTRIDE);
        float4* dst = (float4*)(out + (size_t)(tj * T + ty) * ROWF + (size_t)ti * T * 9);
        #pragma unroll
        for (int c = tx; c < 36; c += 16)
            if (c < w4) dst[c] = src[c];
    }
}

extern "C" void kernel_launch(void* const* d_in, const int* in_sizes, int n_in,
                              void* d_out, int out_size)
{
    const float* xs    = (const float*)d_in[0];
    const float* xsph  = (const float*)d_in[1];
    const float* coord = (const float*)d_in[2];
    // d_in[3] = fc_edge_index (int32, full graph i-major) — structure fixed, unused
    const float* Wsi1 = (const float*)d_in[4];
    const float* Wsi2 = (const float*)d_in[5];
    const float* Wsj1 = (const float*)d_in[6];
    const float* Wsj2 = (const float*)d_in[7];
    const float* Wpi1 = (const float*)d_in[8];
    const float* Wpi2 = (const float*)d_in[9];
    const float* Wpj1 = (const float*)d_in[10];
    const float* Wpj2 = (const float*)d_in[11];
    const float* Wrbf = (const float*)d_in[12];
    float* out = (float*)d_out;

    cudaFuncSetAttribute(node_kernel,
                         cudaFuncAttributeMaxDynamicSharedMemorySize, SMEM_BYTES);

    node_kernel<<<NBLK, 256, SMEM_BYTES>>>(xs, xsph, coord,
                                           Wsi1, Wsi2, Wsj1, Wsj2,
                                           Wpi1, Wpi2, Wpj1, Wpj2);

    int nblocks = NT * (NT + 1) / 2;   // 4465 upper-triangle tiles
    edge_kernel<<<nblocks, 256>>>(Wrbf, out);
}